// round 4
// baseline (speedup 1.0000x reference)
#include <cuda_runtime.h>
#include <math.h>
#include <stdint.h>

#define Nn 8192
#define Dd 256

// ---------------- scratch (device globals; no allocation allowed) ----------------
__device__ float g_Hn[Nn * Dd];     // batch-normed H
__device__ float g_F1[Nn * Dd];     // theta projection -> normalized rows (in place)
__device__ float g_Y[Nn * Dd];      // Hn @ W_out + b_out
__device__ float g_part[2 * 64 * Dd];
__device__ float g_mu[Dd], g_rstd[Dd];
__device__ float g_tval[Nn * 5];
__device__ int   g_tidx[Nn * 5];
__device__ float g_dinv[Nn];

// ---------------- K1a: per-column partial sums over row slices ----------------
__global__ void bn_partial(const float* __restrict__ H) {
    int col = threadIdx.x;                // 256 threads = 256 columns (coalesced)
    int r0 = blockIdx.x * 128;
    float s = 0.f, s2 = 0.f;
    for (int r = 0; r < 128; ++r) {
        float v = H[(size_t)(r0 + r) * Dd + col];
        s += v; s2 += v * v;
    }
    g_part[blockIdx.x * Dd + col] = s;
    g_part[64 * Dd + blockIdx.x * Dd + col] = s2;
}

// ---------------- K1b: finish mean / rstd ----------------
__global__ void bn_finish() {
    int col = threadIdx.x;
    float s = 0.f, s2 = 0.f;
    for (int b = 0; b < 64; ++b) {
        s  += g_part[b * Dd + col];
        s2 += g_part[64 * Dd + b * Dd + col];
    }
    float mu  = s  / (float)Nn;
    float var = s2 / (float)Nn - mu * mu;
    g_mu[col] = mu;
    g_rstd[col] = __frsqrt_rn(var + 1e-5f);
}

// ---------------- K2: apply BN ----------------
__global__ void bn_apply(const float* __restrict__ H,
                         const float* __restrict__ gamma,
                         const float* __restrict__ beta) {
    int idx = blockIdx.x * 256 + threadIdx.x;
    int col = idx & (Dd - 1);
    float v = H[idx];
    g_Hn[idx] = (v - g_mu[col]) * g_rstd[col] * gamma[col] + beta[col];
}

// ---------------- K3: C[8192,256] = Hn @ W + bias (templated destination) ----------------
template <int WHICH>  // 0 -> g_F1 (theta), 1 -> g_Y (out proj)
__global__ __launch_bounds__(256) void gemm_bias(const float* __restrict__ W,
                                                 const float* __restrict__ bias) {
    const int BM = 64, BN = 64, BK = 16;
    __shared__ float As[BK][BM + 4];
    __shared__ float Bs[BK][BN];
    int tid = threadIdx.x;
    int tx = tid & 15, ty = tid >> 4;
    int m0 = blockIdx.x * BM, n0 = blockIdx.y * BN;
    float acc[4][4] = {};
    for (int k0 = 0; k0 < Dd; k0 += BK) {
        __syncthreads();
        int lk = tid & 15, lmb = tid >> 4;
        #pragma unroll
        for (int s = 0; s < 4; ++s) {
            int lm = lmb + s * 16;
            As[lk][lm] = g_Hn[(size_t)(m0 + lm) * Dd + k0 + lk];
        }
        int ln = tid & 63, lkb = tid >> 6;
        #pragma unroll
        for (int s = 0; s < 4; ++s) {
            int lk2 = lkb + s * 4;
            Bs[lk2][ln] = W[(size_t)(k0 + lk2) * Dd + n0 + ln];
        }
        __syncthreads();
        #pragma unroll
        for (int k = 0; k < BK; ++k) {
            float a[4], b[4];
            #pragma unroll
            for (int i = 0; i < 4; ++i) a[i] = As[k][ty * 4 + i];
            #pragma unroll
            for (int j = 0; j < 4; ++j) b[j] = Bs[k][tx * 4 + j];
            #pragma unroll
            for (int i = 0; i < 4; ++i)
                #pragma unroll
                for (int j = 0; j < 4; ++j)
                    acc[i][j] += a[i] * b[j];
        }
    }
    float* C = (WHICH == 0) ? g_F1 : g_Y;
    #pragma unroll
    for (int i = 0; i < 4; ++i)
        #pragma unroll
        for (int j = 0; j < 4; ++j)
            C[(size_t)(m0 + ty * 4 + i) * Dd + n0 + tx * 4 + j] =
                acc[i][j] + bias[n0 + tx * 4 + j];
}

// ---------------- K4: row-normalize g_F1 in place (one warp per row) ----------------
__global__ void rownorm() {
    int w = threadIdx.x >> 5, lane = threadIdx.x & 31;
    int row = blockIdx.x * 8 + w;
    float v[8]; float ss = 0.f;
    #pragma unroll
    for (int s = 0; s < 8; ++s) {
        v[s] = g_F1[(size_t)row * Dd + lane + 32 * s];
        ss += v[s] * v[s];
    }
    #pragma unroll
    for (int o = 16; o; o >>= 1) ss += __shfl_xor_sync(0xffffffffu, ss, o);
    float nrm = fmaxf(__fsqrt_rn(ss), 1e-12f);
    #pragma unroll
    for (int s = 0; s < 8; ++s)
        g_F1[(size_t)row * Dd + lane + 32 * s] = __fdiv_rn(v[s], nrm);
}

// ---------------- K5: fused similarity GEMM + A(dist) + per-row top-5 ----------------
#define TMr 32
#define TNc 128
#define TKK 32

struct SmemGemm { float As[TKK][TMr + 4]; float Bs[TKK][TNc + 4]; };
struct SmemMerge { float val[TMr][80]; int idx[TMr][80]; };
union Smem5 { SmemGemm g; SmemMerge m; };

__device__ __forceinline__ float affinity(float d) {
    d = fminf(1.0f, fmaxf(-1.0f, d));       // clip
    float s = acosf(d);                      // SAM angle
    float e = expf(-0.2f * s);
    float A = __fdiv_rn(1.0f, 1.0f + expf(-e));  // sigmoid
    return fmaxf(A, 0.1f);                   // clamp (never binds, kept for fidelity)
}

__global__ __launch_bounds__(256) void topk_kernel() {
    __shared__ Smem5 sm;
    int tid = threadIdx.x;
    int tx = tid & 15, ty = tid >> 4;
    int rowBase = blockIdx.x * TMr;

    float av[2][5];
    int   ai[2][5];
    #pragma unroll
    for (int r = 0; r < 2; ++r)
        #pragma unroll
        for (int q = 0; q < 5; ++q) { av[r][q] = -1e30f; ai[r][q] = 0x7fffffff; }

    for (int jt = 0; jt < Nn; jt += TNc) {
        float acc[2][8] = {};
        for (int k0 = 0; k0 < Dd; k0 += TKK) {
            __syncthreads();
            int lk = tid & 31, lb = tid >> 5;
            #pragma unroll
            for (int s = 0; s < 4; ++s)
                sm.g.As[lk][lb + 8 * s] =
                    g_F1[(size_t)(rowBase + lb + 8 * s) * Dd + k0 + lk];
            #pragma unroll
            for (int s = 0; s < 16; ++s)
                sm.g.Bs[lk][lb + 8 * s] =
                    g_F1[(size_t)(jt + lb + 8 * s) * Dd + k0 + lk];
            __syncthreads();
            #pragma unroll
            for (int k = 0; k < TKK; ++k) {
                float2 aa = *reinterpret_cast<const float2*>(&sm.g.As[k][ty * 2]);
                float4 b0 = *reinterpret_cast<const float4*>(&sm.g.Bs[k][tx * 8]);
                float4 b1 = *reinterpret_cast<const float4*>(&sm.g.Bs[k][tx * 8 + 4]);
                float b[8] = {b0.x, b0.y, b0.z, b0.w, b1.x, b1.y, b1.z, b1.w};
                #pragma unroll
                for (int c = 0; c < 8; ++c) {
                    acc[0][c] += aa.x * b[c];
                    acc[1][c] += aa.y * b[c];
                }
            }
        }
        // Epilogue: affinity + top-5 insert. Columns arrive in ascending j per
        // thread, so "no displacement on equal value" == lowest-index tie-break.
        #pragma unroll
        for (int c = 0; c < 8; ++c) {
            int j = jt + tx * 8 + c;
            #pragma unroll
            for (int r = 0; r < 2; ++r) {
                float A = affinity(acc[r][c]);
                if (A > av[r][4]) {
                    av[r][4] = A; ai[r][4] = j;
                    #pragma unroll
                    for (int m2 = 3; m2 >= 0; --m2) {
                        if (av[r][m2 + 1] > av[r][m2]) {
                            float tv = av[r][m2]; av[r][m2] = av[r][m2 + 1]; av[r][m2 + 1] = tv;
                            int ti = ai[r][m2]; ai[r][m2] = ai[r][m2 + 1]; ai[r][m2 + 1] = ti;
                        }
                    }
                }
            }
        }
    }

    // Cross-thread merge: 16 sorted 5-lists per row -> global top-5 per row.
    __syncthreads();
    #pragma unroll
    for (int r = 0; r < 2; ++r) {
        int m = ty * 2 + r;
        #pragma unroll
        for (int q = 0; q < 5; ++q) {
            sm.m.val[m][tx * 5 + q] = av[r][q];
            sm.m.idx[m][tx * 5 + q] = ai[r][q];
        }
    }
    __syncthreads();
    if (tid < TMr) {
        int m = tid;
        float bv[5]; int bi[5];
        for (int sel = 0; sel < 5; ++sel) {
            float best = -1e30f; int bidx = 0x7fffffff; int bpos = -1;
            for (int p = 0; p < 80; ++p) {
                float v = sm.m.val[m][p]; int ix = sm.m.idx[m][p];
                if (v > best || (v == best && ix < bidx)) { best = v; bidx = ix; bpos = p; }
            }
            bv[sel] = best; bi[sel] = bidx;
            sm.m.val[m][bpos] = -2e30f;
        }
        // sort kept entries by ascending column index (matches jax's row-sum order)
        #pragma unroll
        for (int a = 0; a < 4; ++a)
            #pragma unroll
            for (int b2 = 0; b2 < 4 - a; ++b2)
                if (bi[b2] > bi[b2 + 1]) {
                    int ti = bi[b2]; bi[b2] = bi[b2 + 1]; bi[b2 + 1] = ti;
                    float tv = bv[b2]; bv[b2] = bv[b2 + 1]; bv[b2 + 1] = tv;
                }
        float sum = 0.f;
        #pragma unroll
        for (int q = 0; q < 5; ++q) sum += bv[q];
        int gr = rowBase + m;
        #pragma unroll
        for (int q = 0; q < 5; ++q) { g_tval[gr * 5 + q] = bv[q]; g_tidx[gr * 5 + q] = bi[q]; }
        g_dinv[gr] = __fdiv_rn(1.0f, __fsqrt_rn(sum));
    }
}

// ---------------- K6: zero + scatter masked A (one block per row) ----------------
__global__ void writeA(float* __restrict__ Aout) {
    int row = blockIdx.x;
    float4* rp = reinterpret_cast<float4*>(Aout + (size_t)row * Nn);
    float4 z = make_float4(0.f, 0.f, 0.f, 0.f);
    #pragma unroll
    for (int s = 0; s < 8; ++s) rp[threadIdx.x + 256 * s] = z;
    __syncthreads();
    if (threadIdx.x < 5) {
        int j = g_tidx[row * 5 + threadIdx.x];
        Aout[(size_t)row * Nn + j] = g_tval[row * 5 + threadIdx.x];
    }
}

// ---------------- K7: out = A_hat @ Y, LeakyReLU (one block per row) ----------------
__global__ void out_gemm(float* __restrict__ Out) {
    __shared__ float sw[5];
    __shared__ int sj[5];
    int row = blockIdx.x;
    if (threadIdx.x < 5) {
        int j = g_tidx[row * 5 + threadIdx.x];
        sj[threadIdx.x] = j;
        sw[threadIdx.x] = (g_dinv[row] * g_tval[row * 5 + threadIdx.x]) * g_dinv[j];
    }
    __syncthreads();
    int c = threadIdx.x;
    float acc = 0.f;
    #pragma unroll
    for (int q = 0; q < 5; ++q)
        acc += sw[q] * g_Y[(size_t)sj[q] * Dd + c];
    Out[(size_t)row * Dd + c] = (acc >= 0.f) ? acc : 0.01f * acc;
}

// ---------------- launcher ----------------
extern "C" void kernel_launch(void* const* d_in, const int* in_sizes, int n_in,
                              void* d_out, int out_size) {
    (void)in_sizes; (void)n_in;
    const float* H     = (const float*)d_in[0];
    const float* gamma = (const float*)d_in[1];
    const float* beta  = (const float*)d_in[2];
    const float* Wt    = (const float*)d_in[3];
    const float* bt    = (const float*)d_in[4];
    const float* Wo    = (const float*)d_in[5];
    const float* bo    = (const float*)d_in[6];
    float* outp = (float*)d_out;

    bn_partial<<<64, 256>>>(H);
    bn_finish<<<1, 256>>>();
    bn_apply<<<(Nn * Dd) / 256, 256>>>(H, gamma, beta);
    gemm_bias<0><<<dim3(Nn / 64, Dd / 64), 256>>>(Wt, bt);   // g_F1 = Hn@Wt + bt
    gemm_bias<1><<<dim3(Nn / 64, Dd / 64), 256>>>(Wo, bo);   // g_Y  = Hn@Wo + bo
    rownorm<<<Nn / 8, 256>>>();
    topk_kernel<<<Nn / TMr, 256>>>();

    long long need_both = (long long)Nn * Dd + (long long)Nn * Nn;
    if ((long long)out_size >= need_both)
        writeA<<<Nn, 256>>>(outp + (size_t)Nn * Dd);
    out_gemm<<<Nn, 256>>>(outp);
}